// round 12
// baseline (speedup 1.0000x reference)
#include <cuda_runtime.h>
#include <cstdint>

#define NVEC 65536
#define DIM  256
#define KCB  4096
#define LOSS_BLOCKS 1024
#define CAND_MAX 40
#define TH 1.0e-3f
#define TROWS 64                 // rows per CTA tile
#define NTILES (NVEC / TROWS)    // 1024

__device__ float    g_x2[NVEC];
__device__ float    g_e2[KCB];
__device__ int      g_idx[NVEC];
__device__ double   g_part[LOSS_BLOCKS];
__device__ uint32_t g_bperm[KCB * DIM / 2];   // bf16x2 fragment-permuted codebook
__device__ int      g_fb_rows[NVEC];
__device__ int      g_fb_count;

__device__ __forceinline__ unsigned fenc(float f) {
    unsigned u = __float_as_uint(f);
    return (u & 0x80000000u) ? ~u : (u | 0x80000000u);
}
__device__ __forceinline__ float fdec(unsigned e) {
    unsigned u = (e & 0x80000000u) ? (e ^ 0x80000000u) : ~e;
    return __uint_as_float(u);
}
// pack bf16x2: lo half = v0, hi half = v1
__device__ __forceinline__ uint32_t bfpack(float v0, float v1) {
    uint32_t r;
    asm("cvt.rn.bf16x2.f32 %0, %1, %2;" : "=r"(r) : "f"(v1), "f"(v0));
    return r;
}

// Exact fp32 distance — identical recipe to rounds 1/4/5/7 (rel_err 0.0)
__device__ __forceinline__ float exact_dist(const float* __restrict__ xr,
                                            const float* __restrict__ cr,
                                            float x2, float e2) {
    const float4* x4 = reinterpret_cast<const float4*>(xr);
    const float4* c4 = reinterpret_cast<const float4*>(cr);
    float acc = 0.f;
    #pragma unroll 8
    for (int q = 0; q < 64; q++) {
        float4 a = x4[q], b = c4[q];
        acc = fmaf(a.x, b.x, acc);
        acc = fmaf(a.y, b.y, acc);
        acc = fmaf(a.z, b.z, acc);
        acc = fmaf(a.w, b.w, acc);
    }
    float t = x2 + e2;
    return t - 2.0f * acc;
}

// ---------------------------------------------------------------------------
__global__ void rownorm_kernel(const float* __restrict__ v, int rows, int which) {
    if (which == 0 && blockIdx.x == 0 && threadIdx.x == 0) g_fb_count = 0;
    int row  = blockIdx.x * (blockDim.x >> 5) + (threadIdx.x >> 5);
    int lane = threadIdx.x & 31;
    if (row >= rows) return;
    const float4* p = reinterpret_cast<const float4*>(v + (size_t)row * DIM);
    float4 a = p[lane];
    float4 b = p[lane + 32];
    float s = ((a.x * a.x + a.y * a.y) + (a.z * a.z + a.w * a.w))
            + ((b.x * b.x + b.y * b.y) + (b.z * b.z + b.w * b.w));
    #pragma unroll
    for (int off = 16; off; off >>= 1)
        s += __shfl_xor_sync(0xffffffffu, s, off);
    if (lane == 0) {
        if (which) g_e2[row] = s;
        else       g_x2[row] = s;
    }
}

// ---------------------------------------------------------------------------
// Pre-convert codebook to bf16 in mma.m16n8k16 B-fragment layout.
// Layout: [chunk 128][kb 4][nb 16][lane 32][reg 2] (u32 = bf16x2)
// ---------------------------------------------------------------------------
__global__ void bperm_kernel(const float* __restrict__ cb) {
    int o = blockIdx.x * 256 + threadIdx.x;    // total 524288
    int reg = o & 1, lane = (o >> 1) & 31, nb = (o >> 6) & 15, kb = (o >> 10) & 3;
    int chunk = o >> 12, kt = chunk >> 2, dc = chunk & 3;
    int gg = lane >> 2, tig = lane & 3;
    int code = kt * 128 + nb * 8 + gg;
    int d0 = dc * 64 + kb * 16 + 2 * tig + reg * 8;
    const float* r = cb + (size_t)code * DIM;
    g_bperm[o] = bfpack(r[d0], r[d0 + 1]);
}

// ---------------------------------------------------------------------------
// bf16 mma.sync distance GEMM + single-pass candidate collection + exact
// fp32 rescore.  CTA tile: 64 rows x 4096 codes, 3 CTAs/SM.
// 8 warps (2 wr x 4 wc); warp tile 32 rows x 32 codes.
// ---------------------------------------------------------------------------
#define MMA16(ac, av, bv) \
    asm volatile("mma.sync.aligned.m16n8k16.row.col.f32.bf16.bf16.f32 " \
        "{%0,%1,%2,%3},{%4,%5,%6,%7},{%8,%9},{%0,%1,%2,%3};" \
        : "+f"((ac)[0]), "+f"((ac)[1]), "+f"((ac)[2]), "+f"((ac)[3]) \
        : "r"((av).x), "r"((av).y), "r"((av).z), "r"((av).w), \
          "r"((bv).x), "r"((bv).y))

// chunk = 16KB: 256 threads x 16B x 4
#define LOAD_CHUNK(c, buf) do {                                               \
    const uint32_t* _src = g_bperm + (size_t)(c) * 4096 + tid * 4;            \
    uint32_t _dst = bsb + (uint32_t)(buf) * 16384u + (uint32_t)tid * 16u;     \
    _Pragma("unroll")                                                         \
    for (int _j = 0; _j < 4; _j++)                                            \
        asm volatile("cp.async.cg.shared.global [%0], [%1], 16;"              \
                     :: "r"(_dst + _j * 4096u), "l"(_src + _j * 1024) : "memory"); \
    asm volatile("cp.async.commit_group;" ::: "memory");                      \
} while (0)

__global__ __launch_bounds__(256, 3)
void vq_mma_kernel(const float* __restrict__ x, const float* __restrict__ cb) {
    extern __shared__ uint32_t dsm[];
    uint32_t* As = dsm;            // 8192 u32 = 32KB (A bf16 fragments, 64 rows)
    uint32_t* Bs = dsm + 8192;     // 8192 u32 = 32KB (2 x 16KB B chunks)
    __shared__ float x2s[TROWS];
    __shared__ unsigned rmin[TROWS];
    __shared__ int scnt[TROWS];
    __shared__ unsigned short cand[TROWS * CAND_MAX];
    __shared__ unsigned long long red[TROWS];

    const int tid = threadIdx.x, lane = tid & 31, warp = tid >> 5;
    const int wr = warp >> 2, wc = warp & 3;
    const int gg = lane >> 2, tig = lane & 3;
    const int row0 = blockIdx.x * TROWS;

    uint32_t bsb;
    asm("{ .reg .u64 t; cvta.to.shared.u64 t, %1; cvt.u32.u64 %0, t; }"
        : "=r"(bsb) : "l"(Bs));

    LOAD_CHUNK(0, 0);   // overlap first B chunk with A prologue

    if (tid < TROWS) {
        x2s[tid] = g_x2[row0 + tid];
        rmin[tid] = 0xFFFFFFFFu;
        scnt[tid] = 0;
        red[tid] = ~0ull;
    }

    // ---- A prologue: 64 x rows -> bf16 fragment layout in smem ----
    {
        const int row = tid >> 2;
        const int p0 = (tid & 3) << 5;
        const int mb = row >> 4;
        const int lrow = (row & 7) << 2;
        const int hi = (row >> 3) & 1;
        const float2* xr2 = reinterpret_cast<const float2*>(
            x + (size_t)(row0 + row) * DIM);
        #pragma unroll 8
        for (int i = 0; i < 32; i++) {
            int p = p0 + i;              // d-pair index, d0 = 2p
            float2 v = xr2[p];
            uint32_t pk = bfpack(v.x, v.y);
            int d0 = p << 1;
            int kbg = d0 >> 4;
            int lfull = lrow | ((d0 & 7) >> 1);
            int reg = hi | (((d0 >> 3) & 1) << 1);
            As[((mb * 16 + kbg) << 7) + (lfull << 2) + reg] = pk;
        }
    }
    __syncthreads();

    float acc[2][4][4];

    for (int kt = 0; kt < 32; kt++) {
        #pragma unroll
        for (int rb = 0; rb < 2; rb++)
            #pragma unroll
            for (int nb = 0; nb < 4; nb++)
                #pragma unroll
                for (int cc = 0; cc < 4; cc++) acc[rb][nb][cc] = 0.f;

        for (int dc = 0; dc < 4; dc++) {
            int ic = kt * 4 + dc;
            if (ic + 1 < 128) {
                LOAD_CHUNK(ic + 1, (ic + 1) & 1);
                asm volatile("cp.async.wait_group 1;" ::: "memory");
            } else {
                asm volatile("cp.async.wait_group 0;" ::: "memory");
            }
            __syncthreads();
            const uint32_t* B = Bs + (ic & 1) * 4096;

            #pragma unroll
            for (int kb = 0; kb < 4; kb++) {
                int kbg = dc * 4 + kb;
                uint4 A4[2];
                uint2 B2[4];
                #pragma unroll
                for (int rb = 0; rb < 2; rb++)
                    A4[rb] = *reinterpret_cast<const uint4*>(
                        As + (((wr * 2 + rb) * 16 + kbg) << 7) + (lane << 2));
                #pragma unroll
                for (int nb = 0; nb < 4; nb++)
                    B2[nb] = *reinterpret_cast<const uint2*>(
                        B + ((kb * 16 + wc * 4 + nb) * 32 + lane) * 2);
                #pragma unroll
                for (int rb = 0; rb < 2; rb++)
                    #pragma unroll
                    for (int nb = 0; nb < 4; nb++)
                        MMA16(acc[rb][nb], A4[rb], B2[nb]);
            }
            __syncthreads();
        }

        // ---- merged single-pass epilogue ----
        // thr = min(stale rmin, this-group min) + TH is a provable superset
        // threshold: winner's approx d* <= group_min + 2B <= thr (TH >= 2B),
        // and stale rmin >= final rmin.  No second pass, no extra barrier.
        float e2v[4][2];
        #pragma unroll
        for (int nb = 0; nb < 4; nb++) {
            int c0 = kt * 128 + wc * 32 + nb * 8 + tig * 2;
            e2v[nb][0] = g_e2[c0];
            e2v[nb][1] = g_e2[c0 + 1];
        }
        #pragma unroll
        for (int rb = 0; rb < 2; rb++) {
            #pragma unroll
            for (int h = 0; h < 2; h++) {
                int r = wr * 32 + rb * 16 + gg + h * 8;
                float stale = fdec(rmin[r]);
                float x2 = x2s[r];
                float dist[8];
                float m = 3.4e38f;
                #pragma unroll
                for (int nb = 0; nb < 4; nb++)
                    #pragma unroll
                    for (int w = 0; w < 2; w++) {
                        float d = (x2 + e2v[nb][w]) - 2.0f * acc[rb][nb][h * 2 + w];
                        dist[nb * 2 + w] = d;
                        m = fminf(m, d);
                    }
                m = fminf(m, __shfl_xor_sync(0xffffffffu, m, 1));
                m = fminf(m, __shfl_xor_sync(0xffffffffu, m, 2));
                float thr = fminf(stale, m) + TH;
                #pragma unroll
                for (int nb = 0; nb < 4; nb++)
                    #pragma unroll
                    for (int w = 0; w < 2; w++) {
                        if (dist[nb * 2 + w] < thr) {
                            int s = atomicAdd(&scnt[r], 1);
                            if (s < CAND_MAX) {
                                int code = kt * 128 + wc * 32 + nb * 8 + tig * 2 + w;
                                cand[r * CAND_MAX + s] = (unsigned short)code;
                            }
                        }
                    }
                if (tig == 0) atomicMin(&rmin[r], fenc(m));
            }
        }
    }

    // ---- exact fp32 rescore ----
    __syncthreads();
    for (int t2 = 0; t2 < TROWS / 8; t2++) {
        int r = warp * (TROWS / 8) + t2;
        int c = scnt[r];
        if (c > CAND_MAX) {
            if (lane == 0) {
                int fi = atomicAdd(&g_fb_count, 1);
                g_fb_rows[fi] = row0 + r;
            }
            continue;
        }
        #pragma unroll
        for (int base = 0; base < CAND_MAX; base += 32) {
            int li = base + lane;
            if (li < c) {
                int idx = cand[r * CAND_MAX + li];
                float dist = exact_dist(x + (size_t)(row0 + r) * DIM,
                                        cb + (size_t)idx * DIM, x2s[r], g_e2[idx]);
                unsigned long long key =
                    ((unsigned long long)fenc(dist) << 32) | (unsigned)idx;
                atomicMin(&red[r], key);
            }
        }
    }
    __syncthreads();
    if (tid < TROWS && scnt[tid] <= CAND_MAX)
        g_idx[row0 + tid] = (int)(red[tid] & 0xFFFFFFFFu);
}

// ---------------------------------------------------------------------------
// Fallback: exact full scan for overflowed rows (parallel: 512 blocks).
// ---------------------------------------------------------------------------
__global__ void fb_kernel(const float* __restrict__ x, const float* __restrict__ cb) {
    __shared__ unsigned long long rr;
    int n = g_fb_count;
    for (int fi = blockIdx.x; fi < n; fi += gridDim.x) {
        int row = g_fb_rows[fi];
        if (threadIdx.x == 0) rr = ~0ull;
        __syncthreads();
        float x2 = g_x2[row];
        for (int c = threadIdx.x; c < KCB; c += blockDim.x) {
            float dist = exact_dist(x + (size_t)row * DIM, cb + (size_t)c * DIM,
                                    x2, g_e2[c]);
            unsigned long long key =
                ((unsigned long long)fenc(dist) << 32) | (unsigned)c;
            atomicMin(&rr, key);
        }
        __syncthreads();
        if (threadIdx.x == 0) g_idx[row] = (int)(rr & 0xFFFFFFFFu);
        __syncthreads();
    }
}

// ---------------------------------------------------------------------------
// Gather + straight-through output + loss partials.
// Warp per row, 2 rows unrolled: idx loaded once per row, MLP = 8.
// ---------------------------------------------------------------------------
__device__ __forceinline__ double st_elem(float4 xv, float4 q, float4& r) {
    float d0 = q.x - xv.x; r.x = xv.x + d0;
    float d1 = q.y - xv.y; r.y = xv.y + d1;
    float d2 = q.z - xv.z; r.z = xv.z + d2;
    float d3 = q.w - xv.w; r.w = xv.w + d3;
    return (double)(d0 * d0) + (double)(d1 * d1)
         + (double)(d2 * d2) + (double)(d3 * d3);
}

__global__ void vq_output_kernel(const float* __restrict__ x,
                                 const float* __restrict__ cb,
                                 float* __restrict__ out) {
    __shared__ double sred[256];
    const int lane = threadIdx.x & 31;
    const int gw = (blockIdx.x * blockDim.x + threadIdx.x) >> 5;
    const int nw = (gridDim.x * blockDim.x) >> 5;
    double lsum = 0.0;

    for (int row = gw * 2; row < NVEC; row += nw * 2) {
        int idx0 = g_idx[row];
        int idx1 = g_idx[row + 1];
        const float4* xr0 = reinterpret_cast<const float4*>(x + (size_t)row * DIM);
        const float4* xr1 = xr0 + 64;
        const float4* cr0 = reinterpret_cast<const float4*>(cb + (size_t)idx0 * DIM);
        const float4* cr1 = reinterpret_cast<const float4*>(cb + (size_t)idx1 * DIM);
        float4* o0 = reinterpret_cast<float4*>(out) + (size_t)row * 64;
        float4* o1 = o0 + 64;

        float4 xa0 = xr0[lane], xb0 = xr0[lane + 32];
        float4 xa1 = xr1[lane], xb1 = xr1[lane + 32];
        float4 qa0 = cr0[lane], qb0 = cr0[lane + 32];
        float4 qa1 = cr1[lane], qb1 = cr1[lane + 32];

        float4 r;
        lsum += st_elem(xa0, qa0, r); o0[lane] = r;
        lsum += st_elem(xb0, qb0, r); o0[lane + 32] = r;
        lsum += st_elem(xa1, qa1, r); o1[lane] = r;
        lsum += st_elem(xb1, qb1, r); o1[lane + 32] = r;
    }
    sred[threadIdx.x] = lsum;
    __syncthreads();
    #pragma unroll
    for (int s = 128; s; s >>= 1) {
        if (threadIdx.x < s) sred[threadIdx.x] += sred[threadIdx.x + s];
        __syncthreads();
    }
    if (threadIdx.x == 0) g_part[blockIdx.x] = sred[0];
}

__global__ void loss_kernel(float* __restrict__ out, int out_size) {
    __shared__ double sred[256];
    double s = 0.0;
    for (int i = threadIdx.x; i < LOSS_BLOCKS; i += 256) s += g_part[i];
    sred[threadIdx.x] = s;
    __syncthreads();
    #pragma unroll
    for (int k = 128; k; k >>= 1) {
        if (threadIdx.x < k) sred[threadIdx.x] += sred[threadIdx.x + k];
        __syncthreads();
    }
    const int nq = NVEC * DIM;
    if (threadIdx.x == 0) {
        double m = sred[0] / (double)nq;
        float mf = (float)m;
        float loss = mf + 0.25f * mf;
        if (out_size == nq + 1)      out[nq] = loss;
        else if (out_size == 1)      out[0] = loss;
        else if (out_size > nq)      out[out_size - 1] = loss;
    }
    for (int i = nq + 1 + threadIdx.x; i < out_size - 1; i += 256) out[i] = 0.f;
}

// ---------------------------------------------------------------------------
extern "C" void kernel_launch(void* const* d_in, const int* in_sizes, int n_in,
                              void* d_out, int out_size) {
    const float* x  = (const float*)d_in[0];
    const float* cb = (const float*)d_in[1];
    if (n_in >= 2 && in_sizes[0] == KCB * DIM && in_sizes[1] == NVEC * DIM) {
        const float* t = x; x = cb; cb = t;
    }
    float* out = (float*)d_out;

    cudaFuncSetAttribute(vq_mma_kernel,
                         cudaFuncAttributeMaxDynamicSharedMemorySize, 65536);

    bperm_kernel<<<KCB * DIM / 2 / 256, 256>>>(cb);
    rownorm_kernel<<<NVEC / 8, 256>>>(x,  NVEC, 0);
    rownorm_kernel<<<KCB  / 8, 256>>>(cb, KCB,  1);
    vq_mma_kernel<<<NTILES, 256, 65536>>>(x, cb);
    fb_kernel<<<512, 256>>>(x, cb);
    vq_output_kernel<<<LOSS_BLOCKS, 256>>>(x, cb, out);
    loss_kernel<<<1, 256>>>(out, out_size);
}

// round 13
// speedup vs baseline: 1.3105x; 1.3105x over previous
#include <cuda_runtime.h>
#include <cstdint>

#define NVEC 65536
#define DIM  256
#define KCB  4096
#define LOSS_BLOCKS 1024
#define CAND_MAX 40
#define TH 1.0e-3f
#define TROWS 64                 // rows per CTA tile
#define NTILES (NVEC / TROWS)    // 1024

__device__ float    g_x2[NVEC];
__device__ float    g_e2[KCB];
__device__ int      g_idx[NVEC];
__device__ double   g_part[LOSS_BLOCKS];
__device__ uint32_t g_bperm[KCB * DIM / 2];   // bf16x2 fragment-permuted codebook
__device__ int      g_fb_rows[NVEC];
__device__ int      g_fb_count;

__device__ __forceinline__ unsigned fenc(float f) {
    unsigned u = __float_as_uint(f);
    return (u & 0x80000000u) ? ~u : (u | 0x80000000u);
}
__device__ __forceinline__ float fdec(unsigned e) {
    unsigned u = (e & 0x80000000u) ? (e ^ 0x80000000u) : ~e;
    return __uint_as_float(u);
}
// pack bf16x2: lo half = v0, hi half = v1
__device__ __forceinline__ uint32_t bfpack(float v0, float v1) {
    uint32_t r;
    asm("cvt.rn.bf16x2.f32 %0, %1, %2;" : "=r"(r) : "f"(v1), "f"(v0));
    return r;
}

// Exact fp32 distance — identical recipe to rounds 1/4/5/7 (rel_err 0.0)
__device__ __forceinline__ float exact_dist(const float* __restrict__ xr,
                                            const float* __restrict__ cr,
                                            float x2, float e2) {
    const float4* x4 = reinterpret_cast<const float4*>(xr);
    const float4* c4 = reinterpret_cast<const float4*>(cr);
    float acc = 0.f;
    #pragma unroll 8
    for (int q = 0; q < 64; q++) {
        float4 a = x4[q], b = c4[q];
        acc = fmaf(a.x, b.x, acc);
        acc = fmaf(a.y, b.y, acc);
        acc = fmaf(a.z, b.z, acc);
        acc = fmaf(a.w, b.w, acc);
    }
    float t = x2 + e2;
    return t - 2.0f * acc;
}

// ---------------------------------------------------------------------------
__global__ void rownorm_kernel(const float* __restrict__ v, int rows, int which) {
    if (which == 0 && blockIdx.x == 0 && threadIdx.x == 0) g_fb_count = 0;
    int row  = blockIdx.x * (blockDim.x >> 5) + (threadIdx.x >> 5);
    int lane = threadIdx.x & 31;
    if (row >= rows) return;
    const float4* p = reinterpret_cast<const float4*>(v + (size_t)row * DIM);
    float4 a = p[lane];
    float4 b = p[lane + 32];
    float s = ((a.x * a.x + a.y * a.y) + (a.z * a.z + a.w * a.w))
            + ((b.x * b.x + b.y * b.y) + (b.z * b.z + b.w * b.w));
    #pragma unroll
    for (int off = 16; off; off >>= 1)
        s += __shfl_xor_sync(0xffffffffu, s, off);
    if (lane == 0) {
        if (which) g_e2[row] = s;
        else       g_x2[row] = s;
    }
}

// ---------------------------------------------------------------------------
// Pre-convert codebook to bf16 in mma.m16n8k16 B-fragment layout.
// Layout: [chunk 128][kb 4][nb 16][lane 32][reg 2] (u32 = bf16x2)
// ---------------------------------------------------------------------------
__global__ void bperm_kernel(const float* __restrict__ cb) {
    int o = blockIdx.x * 256 + threadIdx.x;    // total 524288
    int reg = o & 1, lane = (o >> 1) & 31, nb = (o >> 6) & 15, kb = (o >> 10) & 3;
    int chunk = o >> 12, kt = chunk >> 2, dc = chunk & 3;
    int gg = lane >> 2, tig = lane & 3;
    int code = kt * 128 + nb * 8 + gg;
    int d0 = dc * 64 + kb * 16 + 2 * tig + reg * 8;
    const float* r = cb + (size_t)code * DIM;
    g_bperm[o] = bfpack(r[d0], r[d0 + 1]);
}

// ---------------------------------------------------------------------------
// bf16 mma.sync distance GEMM + two-pass candidate collection + exact fp32
// rescore.  CTA tile: 64 rows x 4096 codes, 3 CTAs/SM (R10 body, verbatim).
// 8 warps (2 wr x 4 wc); warp tile 32 rows x 32 codes.
// ---------------------------------------------------------------------------
#define MMA16(ac, av, bv) \
    asm volatile("mma.sync.aligned.m16n8k16.row.col.f32.bf16.bf16.f32 " \
        "{%0,%1,%2,%3},{%4,%5,%6,%7},{%8,%9},{%0,%1,%2,%3};" \
        : "+f"((ac)[0]), "+f"((ac)[1]), "+f"((ac)[2]), "+f"((ac)[3]) \
        : "r"((av).x), "r"((av).y), "r"((av).z), "r"((av).w), \
          "r"((bv).x), "r"((bv).y))

// chunk = 16KB: 256 threads x 16B x 4
#define LOAD_CHUNK(c, buf) do {                                               \
    const uint32_t* _src = g_bperm + (size_t)(c) * 4096 + tid * 4;            \
    uint32_t _dst = bsb + (uint32_t)(buf) * 16384u + (uint32_t)tid * 16u;     \
    _Pragma("unroll")                                                         \
    for (int _j = 0; _j < 4; _j++)                                            \
        asm volatile("cp.async.cg.shared.global [%0], [%1], 16;"              \
                     :: "r"(_dst + _j * 4096u), "l"(_src + _j * 1024) : "memory"); \
    asm volatile("cp.async.commit_group;" ::: "memory");                      \
} while (0)

__global__ __launch_bounds__(256, 3)
void vq_mma_kernel(const float* __restrict__ x, const float* __restrict__ cb) {
    extern __shared__ uint32_t dsm[];
    uint32_t* As = dsm;            // 8192 u32 = 32KB (A bf16 fragments, 64 rows)
    uint32_t* Bs = dsm + 8192;     // 8192 u32 = 32KB (2 x 16KB B chunks)
    __shared__ float x2s[TROWS];
    __shared__ unsigned rmin[TROWS];
    __shared__ int scnt[TROWS];
    __shared__ unsigned short cand[TROWS * CAND_MAX];
    __shared__ unsigned long long red[TROWS];

    const int tid = threadIdx.x, lane = tid & 31, warp = tid >> 5;
    const int wr = warp >> 2, wc = warp & 3;
    const int gg = lane >> 2, tig = lane & 3;
    const int row0 = blockIdx.x * TROWS;

    uint32_t bsb;
    asm("{ .reg .u64 t; cvta.to.shared.u64 t, %1; cvt.u32.u64 %0, t; }"
        : "=r"(bsb) : "l"(Bs));

    LOAD_CHUNK(0, 0);   // overlap first B chunk with A prologue

    if (tid < TROWS) {
        x2s[tid] = g_x2[row0 + tid];
        rmin[tid] = 0xFFFFFFFFu;
        scnt[tid] = 0;
        red[tid] = ~0ull;
    }

    // ---- A prologue: 64 x rows -> bf16 fragment layout in smem ----
    {
        const int row = tid >> 2;
        const int p0 = (tid & 3) << 5;
        const int mb = row >> 4;
        const int lrow = (row & 7) << 2;
        const int hi = (row >> 3) & 1;
        const float2* xr2 = reinterpret_cast<const float2*>(
            x + (size_t)(row0 + row) * DIM);
        #pragma unroll 8
        for (int i = 0; i < 32; i++) {
            int p = p0 + i;              // d-pair index, d0 = 2p
            float2 v = xr2[p];
            uint32_t pk = bfpack(v.x, v.y);
            int d0 = p << 1;
            int kbg = d0 >> 4;
            int lfull = lrow | ((d0 & 7) >> 1);
            int reg = hi | (((d0 >> 3) & 1) << 1);
            As[((mb * 16 + kbg) << 7) + (lfull << 2) + reg] = pk;
        }
    }
    __syncthreads();

    float acc[2][4][4];

    for (int kt = 0; kt < 32; kt++) {
        #pragma unroll
        for (int rb = 0; rb < 2; rb++)
            #pragma unroll
            for (int nb = 0; nb < 4; nb++)
                #pragma unroll
                for (int cc = 0; cc < 4; cc++) acc[rb][nb][cc] = 0.f;

        for (int dc = 0; dc < 4; dc++) {
            int ic = kt * 4 + dc;
            if (ic + 1 < 128) {
                LOAD_CHUNK(ic + 1, (ic + 1) & 1);
                asm volatile("cp.async.wait_group 1;" ::: "memory");
            } else {
                asm volatile("cp.async.wait_group 0;" ::: "memory");
            }
            __syncthreads();
            const uint32_t* B = Bs + (ic & 1) * 4096;

            #pragma unroll
            for (int kb = 0; kb < 4; kb++) {
                int kbg = dc * 4 + kb;
                uint4 A4[2];
                uint2 B2[4];
                #pragma unroll
                for (int rb = 0; rb < 2; rb++)
                    A4[rb] = *reinterpret_cast<const uint4*>(
                        As + (((wr * 2 + rb) * 16 + kbg) << 7) + (lane << 2));
                #pragma unroll
                for (int nb = 0; nb < 4; nb++)
                    B2[nb] = *reinterpret_cast<const uint2*>(
                        B + ((kb * 16 + wc * 4 + nb) * 32 + lane) * 2);
                #pragma unroll
                for (int rb = 0; rb < 2; rb++)
                    #pragma unroll
                    for (int nb = 0; nb < 4; nb++)
                        MMA16(acc[rb][nb], A4[rb], B2[nb]);
            }
            __syncthreads();
        }

        // ---- epilogue pass 1: dist, shfl-reduced row-min ----
        float e2v[4][2];
        #pragma unroll
        for (int nb = 0; nb < 4; nb++) {
            int c0 = kt * 128 + wc * 32 + nb * 8 + tig * 2;
            e2v[nb][0] = g_e2[c0];
            e2v[nb][1] = g_e2[c0 + 1];
        }
        #pragma unroll
        for (int rb = 0; rb < 2; rb++) {
            #pragma unroll
            for (int h = 0; h < 2; h++) {
                int r = wr * 32 + rb * 16 + gg + h * 8;
                float m = 3.4e38f;
                #pragma unroll
                for (int nb = 0; nb < 4; nb++)
                    #pragma unroll
                    for (int w = 0; w < 2; w++) {
                        int cc = h * 2 + w;
                        float dist = (x2s[r] + e2v[nb][w]) - 2.0f * acc[rb][nb][cc];
                        acc[rb][nb][cc] = dist;
                        m = fminf(m, dist);
                    }
                m = fminf(m, __shfl_xor_sync(0xffffffffu, m, 1));
                m = fminf(m, __shfl_xor_sync(0xffffffffu, m, 2));
                if (tig == 0) atomicMin(&rmin[r], fenc(m));
            }
        }
        __syncthreads();
        // ---- epilogue pass 2: collect with tight running-min threshold ----
        #pragma unroll
        for (int rb = 0; rb < 2; rb++)
            #pragma unroll
            for (int h = 0; h < 2; h++) {
                int r = wr * 32 + rb * 16 + gg + h * 8;
                float thr = fdec(rmin[r]) + TH;
                #pragma unroll
                for (int nb = 0; nb < 4; nb++)
                    #pragma unroll
                    for (int w = 0; w < 2; w++) {
                        if (acc[rb][nb][h * 2 + w] < thr) {
                            int s = atomicAdd(&scnt[r], 1);
                            if (s < CAND_MAX) {
                                int code = kt * 128 + wc * 32 + nb * 8 + tig * 2 + w;
                                cand[r * CAND_MAX + s] = (unsigned short)code;
                            }
                        }
                    }
            }
    }

    // ---- exact fp32 rescore ----
    __syncthreads();
    for (int t2 = 0; t2 < TROWS / 8; t2++) {
        int r = warp * (TROWS / 8) + t2;
        int c = scnt[r];
        if (c > CAND_MAX) {
            if (lane == 0) {
                int fi = atomicAdd(&g_fb_count, 1);
                g_fb_rows[fi] = row0 + r;
            }
            continue;
        }
        #pragma unroll
        for (int base = 0; base < CAND_MAX; base += 32) {
            int li = base + lane;
            if (li < c) {
                int idx = cand[r * CAND_MAX + li];
                float dist = exact_dist(x + (size_t)(row0 + r) * DIM,
                                        cb + (size_t)idx * DIM, x2s[r], g_e2[idx]);
                unsigned long long key =
                    ((unsigned long long)fenc(dist) << 32) | (unsigned)idx;
                atomicMin(&red[r], key);
            }
        }
    }
    __syncthreads();
    if (tid < TROWS && scnt[tid] <= CAND_MAX)
        g_idx[row0 + tid] = (int)(red[tid] & 0xFFFFFFFFu);
}

// ---------------------------------------------------------------------------
// Fallback: exact full scan for overflowed rows (parallel: 512 blocks).
// ---------------------------------------------------------------------------
__global__ void fb_kernel(const float* __restrict__ x, const float* __restrict__ cb) {
    __shared__ unsigned long long rr;
    int n = g_fb_count;
    for (int fi = blockIdx.x; fi < n; fi += gridDim.x) {
        int row = g_fb_rows[fi];
        if (threadIdx.x == 0) rr = ~0ull;
        __syncthreads();
        float x2 = g_x2[row];
        for (int c = threadIdx.x; c < KCB; c += blockDim.x) {
            float dist = exact_dist(x + (size_t)row * DIM, cb + (size_t)c * DIM,
                                    x2, g_e2[c]);
            unsigned long long key =
                ((unsigned long long)fenc(dist) << 32) | (unsigned)c;
            atomicMin(&rr, key);
        }
        __syncthreads();
        if (threadIdx.x == 0) g_idx[row] = (int)(rr & 0xFFFFFFFFu);
        __syncthreads();
    }
}

// ---------------------------------------------------------------------------
// Gather + straight-through output + loss partials.
// Warp per row, 2 rows unrolled: idx loaded once per row, MLP = 8.
// ---------------------------------------------------------------------------
__device__ __forceinline__ double st_elem(float4 xv, float4 q, float4& r) {
    float d0 = q.x - xv.x; r.x = xv.x + d0;
    float d1 = q.y - xv.y; r.y = xv.y + d1;
    float d2 = q.z - xv.z; r.z = xv.z + d2;
    float d3 = q.w - xv.w; r.w = xv.w + d3;
    return (double)(d0 * d0) + (double)(d1 * d1)
         + (double)(d2 * d2) + (double)(d3 * d3);
}

__global__ void vq_output_kernel(const float* __restrict__ x,
                                 const float* __restrict__ cb,
                                 float* __restrict__ out) {
    __shared__ double sred[256];
    const int lane = threadIdx.x & 31;
    const int gw = (blockIdx.x * blockDim.x + threadIdx.x) >> 5;
    const int nw = (gridDim.x * blockDim.x) >> 5;
    double lsum = 0.0;

    for (int row = gw * 2; row < NVEC; row += nw * 2) {
        int idx0 = g_idx[row];
        int idx1 = g_idx[row + 1];
        const float4* xr0 = reinterpret_cast<const float4*>(x + (size_t)row * DIM);
        const float4* xr1 = xr0 + 64;
        const float4* cr0 = reinterpret_cast<const float4*>(cb + (size_t)idx0 * DIM);
        const float4* cr1 = reinterpret_cast<const float4*>(cb + (size_t)idx1 * DIM);
        float4* o0 = reinterpret_cast<float4*>(out) + (size_t)row * 64;
        float4* o1 = o0 + 64;

        float4 xa0 = xr0[lane], xb0 = xr0[lane + 32];
        float4 xa1 = xr1[lane], xb1 = xr1[lane + 32];
        float4 qa0 = cr0[lane], qb0 = cr0[lane + 32];
        float4 qa1 = cr1[lane], qb1 = cr1[lane + 32];

        float4 r;
        lsum += st_elem(xa0, qa0, r); o0[lane] = r;
        lsum += st_elem(xb0, qb0, r); o0[lane + 32] = r;
        lsum += st_elem(xa1, qa1, r); o1[lane] = r;
        lsum += st_elem(xb1, qb1, r); o1[lane + 32] = r;
    }
    sred[threadIdx.x] = lsum;
    __syncthreads();
    #pragma unroll
    for (int s = 128; s; s >>= 1) {
        if (threadIdx.x < s) sred[threadIdx.x] += sred[threadIdx.x + s];
        __syncthreads();
    }
    if (threadIdx.x == 0) g_part[blockIdx.x] = sred[0];
}

__global__ void loss_kernel(float* __restrict__ out, int out_size) {
    __shared__ double sred[256];
    double s = 0.0;
    for (int i = threadIdx.x; i < LOSS_BLOCKS; i += 256) s += g_part[i];
    sred[threadIdx.x] = s;
    __syncthreads();
    #pragma unroll
    for (int k = 128; k; k >>= 1) {
        if (threadIdx.x < k) sred[threadIdx.x] += sred[threadIdx.x + k];
        __syncthreads();
    }
    const int nq = NVEC * DIM;
    if (threadIdx.x == 0) {
        double m = sred[0] / (double)nq;
        float mf = (float)m;
        float loss = mf + 0.25f * mf;
        if (out_size == nq + 1)      out[nq] = loss;
        else if (out_size == 1)      out[0] = loss;
        else if (out_size > nq)      out[out_size - 1] = loss;
    }
    for (int i = nq + 1 + threadIdx.x; i < out_size - 1; i += 256) out[i] = 0.f;
}

// ---------------------------------------------------------------------------
extern "C" void kernel_launch(void* const* d_in, const int* in_sizes, int n_in,
                              void* d_out, int out_size) {
    const float* x  = (const float*)d_in[0];
    const float* cb = (const float*)d_in[1];
    if (n_in >= 2 && in_sizes[0] == KCB * DIM && in_sizes[1] == NVEC * DIM) {
        const float* t = x; x = cb; cb = t;
    }
    float* out = (float*)d_out;

    cudaFuncSetAttribute(vq_mma_kernel,
                         cudaFuncAttributeMaxDynamicSharedMemorySize, 65536);

    bperm_kernel<<<KCB * DIM / 2 / 256, 256>>>(cb);
    rownorm_kernel<<<NVEC / 8, 256>>>(x,  NVEC, 0);
    rownorm_kernel<<<KCB  / 8, 256>>>(cb, KCB,  1);
    vq_mma_kernel<<<NTILES, 256, 65536>>>(x, cb);
    fb_kernel<<<512, 256>>>(x, cb);
    vq_output_kernel<<<LOSS_BLOCKS, 256>>>(x, cb, out);
    loss_kernel<<<1, 256>>>(out, out_size);
}

// round 14
// speedup vs baseline: 1.3566x; 1.0352x over previous
#include <cuda_runtime.h>
#include <cstdint>

#define NVEC 65536
#define DIM  256
#define KCB  4096
#define LOSS_BLOCKS 1024
#define CAND_MAX 40
#define TH 1.0e-3f
#define TROWS 64                 // rows per CTA tile
#define NTILES (NVEC / TROWS)    // 1024

__device__ float    g_x2[NVEC];
__device__ float    g_e2[KCB];
__device__ int      g_idx[NVEC];
__device__ double   g_part[LOSS_BLOCKS];
__device__ uint32_t g_bperm[KCB * DIM / 2];   // bf16x2 fragment-permuted codebook
__device__ int      g_fb_rows[NVEC];
__device__ int      g_fb_count;

__device__ __forceinline__ unsigned fenc(float f) {
    unsigned u = __float_as_uint(f);
    return (u & 0x80000000u) ? ~u : (u | 0x80000000u);
}
__device__ __forceinline__ float fdec(unsigned e) {
    unsigned u = (e & 0x80000000u) ? (e ^ 0x80000000u) : ~e;
    return __uint_as_float(u);
}
// pack bf16x2: lo half = v0, hi half = v1
__device__ __forceinline__ uint32_t bfpack(float v0, float v1) {
    uint32_t r;
    asm("cvt.rn.bf16x2.f32 %0, %1, %2;" : "=r"(r) : "f"(v1), "f"(v0));
    return r;
}

// Exact fp32 distance — identical recipe to rounds 1/4/5/7 (rel_err 0.0)
__device__ __forceinline__ float exact_dist(const float* __restrict__ xr,
                                            const float* __restrict__ cr,
                                            float x2, float e2) {
    const float4* x4 = reinterpret_cast<const float4*>(xr);
    const float4* c4 = reinterpret_cast<const float4*>(cr);
    float acc = 0.f;
    #pragma unroll 8
    for (int q = 0; q < 64; q++) {
        float4 a = x4[q], b = c4[q];
        acc = fmaf(a.x, b.x, acc);
        acc = fmaf(a.y, b.y, acc);
        acc = fmaf(a.z, b.z, acc);
        acc = fmaf(a.w, b.w, acc);
    }
    float t = x2 + e2;
    return t - 2.0f * acc;
}

// ---------------------------------------------------------------------------
__global__ void rownorm_kernel(const float* __restrict__ v, int rows, int which) {
    if (which == 0 && blockIdx.x == 0 && threadIdx.x == 0) g_fb_count = 0;
    int row  = blockIdx.x * (blockDim.x >> 5) + (threadIdx.x >> 5);
    int lane = threadIdx.x & 31;
    if (row >= rows) return;
    const float4* p = reinterpret_cast<const float4*>(v + (size_t)row * DIM);
    float4 a = p[lane];
    float4 b = p[lane + 32];
    float s = ((a.x * a.x + a.y * a.y) + (a.z * a.z + a.w * a.w))
            + ((b.x * b.x + b.y * b.y) + (b.z * b.z + b.w * b.w));
    #pragma unroll
    for (int off = 16; off; off >>= 1)
        s += __shfl_xor_sync(0xffffffffu, s, off);
    if (lane == 0) {
        if (which) g_e2[row] = s;
        else       g_x2[row] = s;
    }
}

// ---------------------------------------------------------------------------
// Codebook -> bf16 B fragments, nb-PAIRED layout.
// Linear: [chunk 128][kb 4][qp 8][lane 32][reg 4] (u32 = bf16x2)
//   chunk = kt*4 + dc covers codes kt*128.. and d = dc*64..+63
//   frag = reg>>1, r = reg&1
//   code = kt*128 + qp*16 + frag*8 + (lane>>2)
//   d0   = dc*64 + kb*16 + 2*(lane&3) + r*8   (pair d0, d0+1)
// Per-fragment (lane,reg) mapping identical to the validated R7 layout;
// only fragment ordering changed (two n8 frags per 16B line).
// ---------------------------------------------------------------------------
__global__ void bperm_kernel(const float* __restrict__ cb) {
    int o = blockIdx.x * 256 + threadIdx.x;    // total 524288
    int reg = o & 3, lane = (o >> 2) & 31, qp = (o >> 7) & 7, kb = (o >> 10) & 3;
    int chunk = o >> 12, kt = chunk >> 2, dc = chunk & 3;
    int frag = reg >> 1, r = reg & 1;
    int code = kt * 128 + qp * 16 + frag * 8 + (lane >> 2);
    int d0 = dc * 64 + kb * 16 + 2 * (lane & 3) + r * 8;
    const float* rw = cb + (size_t)code * DIM;
    g_bperm[o] = bfpack(rw[d0], rw[d0 + 1]);
}

// ---------------------------------------------------------------------------
// bf16 mma.sync distance GEMM + two-pass candidate collection + exact fp32
// rescore.  CTA tile: 64 rows x 4096 codes, 2 CTAs/SM.
// 8 warps = 2 wr x 4 wn; warp tile 32 rows x 64 codes; CTA super-tile
// 64 rows x 256 codes per iteration (two 128-code chunks per ring step).
// ---------------------------------------------------------------------------
#define MMA16(ac, av, bv) \
    asm volatile("mma.sync.aligned.m16n8k16.row.col.f32.bf16.bf16.f32 " \
        "{%0,%1,%2,%3},{%4,%5,%6,%7},{%8,%9},{%0,%1,%2,%3};" \
        : "+f"((ac)[0]), "+f"((ac)[1]), "+f"((ac)[2]), "+f"((ac)[3]) \
        : "r"((av).x), "r"((av).y), "r"((av).z), "r"((av).w), \
          "r"((bv).x), "r"((bv).y))

// pair p -> chunks c0 = 8*(p>>2)+(p&3) and c0+4 ; 32KB into slot (p&1)
#define LOAD_PAIR(p) do {                                                     \
    int _skt = (p) >> 2, _dc = (p) & 3;                                       \
    int _c0 = _skt * 8 + _dc;                                                 \
    const uint32_t* _s0 = g_bperm + (size_t)_c0 * 4096 + tid * 4;             \
    const uint32_t* _s1 = _s0 + 4 * 4096;                                     \
    uint32_t _d = bsb + (uint32_t)((p) & 1) * 32768u + (uint32_t)tid * 16u;   \
    _Pragma("unroll")                                                         \
    for (int _j = 0; _j < 4; _j++) {                                          \
        asm volatile("cp.async.cg.shared.global [%0], [%1], 16;"              \
                     :: "r"(_d + _j * 4096u), "l"(_s0 + _j * 1024) : "memory");\
        asm volatile("cp.async.cg.shared.global [%0], [%1], 16;"              \
                     :: "r"(_d + 16384u + _j * 4096u), "l"(_s1 + _j * 1024) : "memory");\
    }                                                                         \
    asm volatile("cp.async.commit_group;" ::: "memory");                      \
} while (0)

__global__ __launch_bounds__(256, 2)
void vq_mma_kernel(const float* __restrict__ x, const float* __restrict__ cb) {
    extern __shared__ uint32_t dsm[];
    uint32_t* As = dsm;            //  8192 u32 = 32KB (A bf16 fragments, 64 rows)
    uint32_t* Bs = dsm + 8192;     // 16384 u32 = 64KB (2 x 32KB B pair slots)
    __shared__ float x2s[TROWS];
    __shared__ unsigned rmin[TROWS];
    __shared__ int scnt[TROWS];
    __shared__ unsigned short cand[TROWS * CAND_MAX];
    __shared__ unsigned long long red[TROWS];

    const int tid = threadIdx.x, lane = tid & 31, warp = tid >> 5;
    const int wr = warp >> 2, wn = warp & 3;
    const int gg = lane >> 2, tig = lane & 3;
    const int qbase = (wn & 1) * 4;      // q-pair base within the 128-code chunk
    const int chalf = wn >> 1;           // which chunk of the pair
    const int row0 = blockIdx.x * TROWS;

    uint32_t bsb;
    asm("{ .reg .u64 t; cvta.to.shared.u64 t, %1; cvt.u32.u64 %0, t; }"
        : "=r"(bsb) : "l"(Bs));

    LOAD_PAIR(0);
    LOAD_PAIR(1);

    if (tid < TROWS) {
        x2s[tid] = g_x2[row0 + tid];
        rmin[tid] = 0xFFFFFFFFu;
        scnt[tid] = 0;
        red[tid] = ~0ull;
    }

    // ---- A prologue: 64 x rows -> bf16 fragment layout in smem ----
    {
        const int row = tid >> 2;
        const int p0 = (tid & 3) << 5;
        const int mb = row >> 4;
        const int lrow = (row & 7) << 2;
        const int hi = (row >> 3) & 1;
        const float2* xr2 = reinterpret_cast<const float2*>(
            x + (size_t)(row0 + row) * DIM);
        #pragma unroll 8
        for (int i = 0; i < 32; i++) {
            int p = p0 + i;              // d-pair index, d0 = 2p
            float2 v = xr2[p];
            uint32_t pk = bfpack(v.x, v.y);
            int d0 = p << 1;
            int kbg = d0 >> 4;
            int lfull = lrow | ((d0 & 7) >> 1);
            int reg = hi | (((d0 >> 3) & 1) << 1);
            As[((mb * 16 + kbg) << 7) + (lfull << 2) + reg] = pk;
        }
    }
    __syncthreads();

    float acc[2][8][4];

    for (int skt = 0; skt < 16; skt++) {
        #pragma unroll
        for (int rb = 0; rb < 2; rb++)
            #pragma unroll
            for (int nq = 0; nq < 8; nq++)
                #pragma unroll
                for (int cc = 0; cc < 4; cc++) acc[rb][nq][cc] = 0.f;

        for (int dc = 0; dc < 4; dc++) {
            int p = skt * 4 + dc;
            asm volatile("cp.async.wait_group 1;" ::: "memory");
            __syncthreads();
            const uint32_t* Bc = Bs + (p & 1) * 8192 + chalf * 4096;

            #pragma unroll
            for (int l = 0; l < 4; l++) {
                int kbg = dc * 4 + l;
                uint4 A4[2];
                #pragma unroll
                for (int rb = 0; rb < 2; rb++)
                    A4[rb] = *reinterpret_cast<const uint4*>(
                        As + (((wr * 2 + rb) * 16 + kbg) << 7) + (lane << 2));
                #pragma unroll
                for (int j = 0; j < 4; j++) {
                    uint4 Bp = *reinterpret_cast<const uint4*>(
                        Bc + (((l * 8 + qbase + j) * 32 + lane) << 2));
                    uint2 b0; b0.x = Bp.x; b0.y = Bp.y;
                    uint2 b1; b1.x = Bp.z; b1.y = Bp.w;
                    #pragma unroll
                    for (int rb = 0; rb < 2; rb++) {
                        MMA16(acc[rb][j * 2],     A4[rb], b0);
                        MMA16(acc[rb][j * 2 + 1], A4[rb], b1);
                    }
                }
            }
            __syncthreads();
            if (p + 2 < 64) LOAD_PAIR(p + 2);
        }

        // ---- epilogue pass 1: dist, shfl-reduced row-min ----
        const int cbase = skt * 256 + wn * 64;
        float e2v[8][2];
        #pragma unroll
        for (int nq = 0; nq < 8; nq++) {
            int c0 = cbase + nq * 8 + tig * 2;
            e2v[nq][0] = g_e2[c0];
            e2v[nq][1] = g_e2[c0 + 1];
        }
        #pragma unroll
        for (int rb = 0; rb < 2; rb++) {
            #pragma unroll
            for (int h = 0; h < 2; h++) {
                int r = wr * 32 + rb * 16 + gg + h * 8;
                float m = 3.4e38f;
                #pragma unroll
                for (int nq = 0; nq < 8; nq++)
                    #pragma unroll
                    for (int w = 0; w < 2; w++) {
                        int cc = h * 2 + w;
                        float dist = (x2s[r] + e2v[nq][w]) - 2.0f * acc[rb][nq][cc];
                        acc[rb][nq][cc] = dist;
                        m = fminf(m, dist);
                    }
                m = fminf(m, __shfl_xor_sync(0xffffffffu, m, 1));
                m = fminf(m, __shfl_xor_sync(0xffffffffu, m, 2));
                if (tig == 0) atomicMin(&rmin[r], fenc(m));
            }
        }
        __syncthreads();
        // ---- epilogue pass 2: collect with tight running-min threshold ----
        #pragma unroll
        for (int rb = 0; rb < 2; rb++)
            #pragma unroll
            for (int h = 0; h < 2; h++) {
                int r = wr * 32 + rb * 16 + gg + h * 8;
                float thr = fdec(rmin[r]) + TH;
                #pragma unroll
                for (int nq = 0; nq < 8; nq++)
                    #pragma unroll
                    for (int w = 0; w < 2; w++) {
                        if (acc[rb][nq][h * 2 + w] < thr) {
                            int s = atomicAdd(&scnt[r], 1);
                            if (s < CAND_MAX) {
                                int code = cbase + nq * 8 + tig * 2 + w;
                                cand[r * CAND_MAX + s] = (unsigned short)code;
                            }
                        }
                    }
            }
    }

    // ---- exact fp32 rescore ----
    __syncthreads();
    for (int t2 = 0; t2 < TROWS / 8; t2++) {
        int r = warp * (TROWS / 8) + t2;
        int c = scnt[r];
        if (c > CAND_MAX) {
            if (lane == 0) {
                int fi = atomicAdd(&g_fb_count, 1);
                g_fb_rows[fi] = row0 + r;
            }
            continue;
        }
        #pragma unroll
        for (int base = 0; base < CAND_MAX; base += 32) {
            int li = base + lane;
            if (li < c) {
                int idx = cand[r * CAND_MAX + li];
                float dist = exact_dist(x + (size_t)(row0 + r) * DIM,
                                        cb + (size_t)idx * DIM, x2s[r], g_e2[idx]);
                unsigned long long key =
                    ((unsigned long long)fenc(dist) << 32) | (unsigned)idx;
                atomicMin(&red[r], key);
            }
        }
    }
    __syncthreads();
    if (tid < TROWS && scnt[tid] <= CAND_MAX)
        g_idx[row0 + tid] = (int)(red[tid] & 0xFFFFFFFFu);
}

// ---------------------------------------------------------------------------
// Fallback: exact full scan for overflowed rows (parallel: 512 blocks).
// ---------------------------------------------------------------------------
__global__ void fb_kernel(const float* __restrict__ x, const float* __restrict__ cb) {
    __shared__ unsigned long long rr;
    int n = g_fb_count;
    for (int fi = blockIdx.x; fi < n; fi += gridDim.x) {
        int row = g_fb_rows[fi];
        if (threadIdx.x == 0) rr = ~0ull;
        __syncthreads();
        float x2 = g_x2[row];
        for (int c = threadIdx.x; c < KCB; c += blockDim.x) {
            float dist = exact_dist(x + (size_t)row * DIM, cb + (size_t)c * DIM,
                                    x2, g_e2[c]);
            unsigned long long key =
                ((unsigned long long)fenc(dist) << 32) | (unsigned)c;
            atomicMin(&rr, key);
        }
        __syncthreads();
        if (threadIdx.x == 0) g_idx[row] = (int)(rr & 0xFFFFFFFFu);
        __syncthreads();
    }
}

// ---------------------------------------------------------------------------
// Gather + straight-through output + loss partials.
// Warp per row, 2 rows unrolled: idx loaded once per row, MLP = 8.
// ---------------------------------------------------------------------------
__device__ __forceinline__ double st_elem(float4 xv, float4 q, float4& r) {
    float d0 = q.x - xv.x; r.x = xv.x + d0;
    float d1 = q.y - xv.y; r.y = xv.y + d1;
    float d2 = q.z - xv.z; r.z = xv.z + d2;
    float d3 = q.w - xv.w; r.w = xv.w + d3;
    return (double)(d0 * d0) + (double)(d1 * d1)
         + (double)(d2 * d2) + (double)(d3 * d3);
}

__global__ void vq_output_kernel(const float* __restrict__ x,
                                 const float* __restrict__ cb,
                                 float* __restrict__ out) {
    __shared__ double sred[256];
    const int lane = threadIdx.x & 31;
    const int gw = (blockIdx.x * blockDim.x + threadIdx.x) >> 5;
    const int nw = (gridDim.x * blockDim.x) >> 5;
    double lsum = 0.0;

    for (int row = gw * 2; row < NVEC; row += nw * 2) {
        int idx0 = g_idx[row];
        int idx1 = g_idx[row + 1];
        const float4* xr0 = reinterpret_cast<const float4*>(x + (size_t)row * DIM);
        const float4* xr1 = xr0 + 64;
        const float4* cr0 = reinterpret_cast<const float4*>(cb + (size_t)idx0 * DIM);
        const float4* cr1 = reinterpret_cast<const float4*>(cb + (size_t)idx1 * DIM);
        float4* o0 = reinterpret_cast<float4*>(out) + (size_t)row * 64;
        float4* o1 = o0 + 64;

        float4 xa0 = xr0[lane], xb0 = xr0[lane + 32];
        float4 xa1 = xr1[lane], xb1 = xr1[lane + 32];
        float4 qa0 = cr0[lane], qb0 = cr0[lane + 32];
        float4 qa1 = cr1[lane], qb1 = cr1[lane + 32];

        float4 r;
        lsum += st_elem(xa0, qa0, r); o0[lane] = r;
        lsum += st_elem(xb0, qb0, r); o0[lane + 32] = r;
        lsum += st_elem(xa1, qa1, r); o1[lane] = r;
        lsum += st_elem(xb1, qb1, r); o1[lane + 32] = r;
    }
    sred[threadIdx.x] = lsum;
    __syncthreads();
    #pragma unroll
    for (int s = 128; s; s >>= 1) {
        if (threadIdx.x < s) sred[threadIdx.x] += sred[threadIdx.x + s];
        __syncthreads();
    }
    if (threadIdx.x == 0) g_part[blockIdx.x] = sred[0];
}

__global__ void loss_kernel(float* __restrict__ out, int out_size) {
    __shared__ double sred[256];
    double s = 0.0;
    for (int i = threadIdx.x; i < LOSS_BLOCKS; i += 256) s += g_part[i];
    sred[threadIdx.x] = s;
    __syncthreads();
    #pragma unroll
    for (int k = 128; k; k >>= 1) {
        if (threadIdx.x < k) sred[threadIdx.x] += sred[threadIdx.x + k];
        __syncthreads();
    }
    const int nq = NVEC * DIM;
    if (threadIdx.x == 0) {
        double m = sred[0] / (double)nq;
        float mf = (float)m;
        float loss = mf + 0.25f * mf;
        if (out_size == nq + 1)      out[nq] = loss;
        else if (out_size == 1)      out[0] = loss;
        else if (out_size > nq)      out[out_size - 1] = loss;
    }
    for (int i = nq + 1 + threadIdx.x; i < out_size - 1; i += 256) out[i] = 0.f;
}

// ---------------------------------------------------------------------------
extern "C" void kernel_launch(void* const* d_in, const int* in_sizes, int n_in,
                              void* d_out, int out_size) {
    const float* x  = (const float*)d_in[0];
    const float* cb = (const float*)d_in[1];
    if (n_in >= 2 && in_sizes[0] == KCB * DIM && in_sizes[1] == NVEC * DIM) {
        const float* t = x; x = cb; cb = t;
    }
    float* out = (float*)d_out;

    cudaFuncSetAttribute(vq_mma_kernel,
                         cudaFuncAttributeMaxDynamicSharedMemorySize, 98304);

    bperm_kernel<<<KCB * DIM / 2 / 256, 256>>>(cb);
    rownorm_kernel<<<NVEC / 8, 256>>>(x,  NVEC, 0);
    rownorm_kernel<<<KCB  / 8, 256>>>(cb, KCB,  1);
    vq_mma_kernel<<<NTILES, 256, 98304>>>(x, cb);
    fb_kernel<<<512, 256>>>(x, cb);
    vq_output_kernel<<<LOSS_BLOCKS, 256>>>(x, cb, out);
    loss_kernel<<<1, 256>>>(out, out_size);
}

// round 15
// speedup vs baseline: 1.3683x; 1.0086x over previous
#include <cuda_runtime.h>
#include <cstdint>

#define NVEC 65536
#define DIM  256
#define KCB  4096
#define LOSS_BLOCKS 1024
#define CAND_MAX 40
#define TH 1.0e-3f
#define TROWS 64                 // rows per CTA tile
#define NTILES (NVEC / TROWS)    // 1024

__device__ float    g_x2[NVEC];
__device__ float    g_e2[KCB];
__device__ int      g_idx[NVEC];
__device__ double   g_part[LOSS_BLOCKS];
__device__ uint32_t g_bperm[KCB * DIM / 2];   // bf16x2 fragment-permuted codebook
__device__ int      g_fb_rows[NVEC];
__device__ int      g_fb_count;

__device__ __forceinline__ unsigned fenc(float f) {
    unsigned u = __float_as_uint(f);
    return (u & 0x80000000u) ? ~u : (u | 0x80000000u);
}
__device__ __forceinline__ float fdec(unsigned e) {
    unsigned u = (e & 0x80000000u) ? (e ^ 0x80000000u) : ~e;
    return __uint_as_float(u);
}
// pack bf16x2: lo half = v0, hi half = v1
__device__ __forceinline__ uint32_t bfpack(float v0, float v1) {
    uint32_t r;
    asm("cvt.rn.bf16x2.f32 %0, %1, %2;" : "=r"(r) : "f"(v1), "f"(v0));
    return r;
}

// Exact fp32 distance — identical recipe to rounds 1/4/5/7 (rel_err 0.0)
__device__ __forceinline__ float exact_dist(const float* __restrict__ xr,
                                            const float* __restrict__ cr,
                                            float x2, float e2) {
    const float4* x4 = reinterpret_cast<const float4*>(xr);
    const float4* c4 = reinterpret_cast<const float4*>(cr);
    float acc = 0.f;
    #pragma unroll 8
    for (int q = 0; q < 64; q++) {
        float4 a = x4[q], b = c4[q];
        acc = fmaf(a.x, b.x, acc);
        acc = fmaf(a.y, b.y, acc);
        acc = fmaf(a.z, b.z, acc);
        acc = fmaf(a.w, b.w, acc);
    }
    float t = x2 + e2;
    return t - 2.0f * acc;
}

// Row squared-norm for one row by one warp — IDENTICAL arithmetic to the
// original rownorm_kernel (same loads, same pairwise + shfl tree order).
__device__ __forceinline__ float warp_rownorm(const float* __restrict__ vrow,
                                              int lane) {
    const float4* p = reinterpret_cast<const float4*>(vrow);
    float4 a = p[lane];
    float4 b = p[lane + 32];
    float s = ((a.x * a.x + a.y * a.y) + (a.z * a.z + a.w * a.w))
            + ((b.x * b.x + b.y * b.y) + (b.z * b.z + b.w * b.w));
    #pragma unroll
    for (int off = 16; off; off >>= 1)
        s += __shfl_xor_sync(0xffffffffu, s, off);
    return s;
}

// ---------------------------------------------------------------------------
// Codebook row norms (e2). Small: 4096 rows.
// ---------------------------------------------------------------------------
__global__ void rownorm_e_kernel(const float* __restrict__ v) {
    int row  = blockIdx.x * (blockDim.x >> 5) + (threadIdx.x >> 5);
    int lane = threadIdx.x & 31;
    float s = warp_rownorm(v + (size_t)row * DIM, lane);
    if (lane == 0) g_e2[row] = s;
}

// ---------------------------------------------------------------------------
// Codebook -> bf16 B fragments, nb-PAIRED layout (validated R13).
// Linear: [chunk 128][kb 4][qp 8][lane 32][reg 4] (u32 = bf16x2)
// Also resets g_fb_count (was in rownorm_x, now fused away).
// ---------------------------------------------------------------------------
__global__ void bperm_kernel(const float* __restrict__ cb) {
    int o = blockIdx.x * 256 + threadIdx.x;    // total 524288
    if (o == 0) g_fb_count = 0;
    int reg = o & 3, lane = (o >> 2) & 31, qp = (o >> 7) & 7, kb = (o >> 10) & 3;
    int chunk = o >> 12, kt = chunk >> 2, dc = chunk & 3;
    int frag = reg >> 1, r = reg & 1;
    int code = kt * 128 + qp * 16 + frag * 8 + (lane >> 2);
    int d0 = dc * 64 + kb * 16 + 2 * (lane & 3) + r * 8;
    const float* rw = cb + (size_t)code * DIM;
    g_bperm[o] = bfpack(rw[d0], rw[d0 + 1]);
}

// ---------------------------------------------------------------------------
// bf16 mma.sync distance GEMM + two-pass candidate collection + exact fp32
// rescore + FUSED x-row-norm prologue.
// CTA tile: 64 rows x 4096 codes, 2 CTAs/SM.
// 8 warps = 2 wr x 4 wn; warp tile 32 rows x 64 codes; CTA super-tile
// 64 rows x 256 codes per iteration (two 128-code chunks per ring step).
// ---------------------------------------------------------------------------
#define MMA16(ac, av, bv) \
    asm volatile("mma.sync.aligned.m16n8k16.row.col.f32.bf16.bf16.f32 " \
        "{%0,%1,%2,%3},{%4,%5,%6,%7},{%8,%9},{%0,%1,%2,%3};" \
        : "+f"((ac)[0]), "+f"((ac)[1]), "+f"((ac)[2]), "+f"((ac)[3]) \
        : "r"((av).x), "r"((av).y), "r"((av).z), "r"((av).w), \
          "r"((bv).x), "r"((bv).y))

// pair p -> chunks c0 = 8*(p>>2)+(p&3) and c0+4 ; 32KB into slot (p&1)
#define LOAD_PAIR(p) do {                                                     \
    int _skt = (p) >> 2, _dc = (p) & 3;                                       \
    int _c0 = _skt * 8 + _dc;                                                 \
    const uint32_t* _s0 = g_bperm + (size_t)_c0 * 4096 + tid * 4;             \
    const uint32_t* _s1 = _s0 + 4 * 4096;                                     \
    uint32_t _d = bsb + (uint32_t)((p) & 1) * 32768u + (uint32_t)tid * 16u;   \
    _Pragma("unroll")                                                         \
    for (int _j = 0; _j < 4; _j++) {                                          \
        asm volatile("cp.async.cg.shared.global [%0], [%1], 16;"              \
                     :: "r"(_d + _j * 4096u), "l"(_s0 + _j * 1024) : "memory");\
        asm volatile("cp.async.cg.shared.global [%0], [%1], 16;"              \
                     :: "r"(_d + 16384u + _j * 4096u), "l"(_s1 + _j * 1024) : "memory");\
    }                                                                         \
    asm volatile("cp.async.commit_group;" ::: "memory");                      \
} while (0)

__global__ __launch_bounds__(256, 2)
void vq_mma_kernel(const float* __restrict__ x, const float* __restrict__ cb) {
    extern __shared__ uint32_t dsm[];
    uint32_t* As = dsm;            //  8192 u32 = 32KB (A bf16 fragments, 64 rows)
    uint32_t* Bs = dsm + 8192;     // 16384 u32 = 64KB (2 x 32KB B pair slots)
    __shared__ float x2s[TROWS];
    __shared__ unsigned rmin[TROWS];
    __shared__ int scnt[TROWS];
    __shared__ unsigned short cand[TROWS * CAND_MAX];
    __shared__ unsigned long long red[TROWS];

    const int tid = threadIdx.x, lane = tid & 31, warp = tid >> 5;
    const int wr = warp >> 2, wn = warp & 3;
    const int gg = lane >> 2, tig = lane & 3;
    const int qbase = (wn & 1) * 4;      // q-pair base within the 128-code chunk
    const int chalf = wn >> 1;           // which chunk of the pair
    const int row0 = blockIdx.x * TROWS;

    uint32_t bsb;
    asm("{ .reg .u64 t; cvta.to.shared.u64 t, %1; cvt.u32.u64 %0, t; }"
        : "=r"(bsb) : "l"(Bs));

    LOAD_PAIR(0);
    LOAD_PAIR(1);

    if (tid < TROWS) {
        rmin[tid] = 0xFFFFFFFFu;
        scnt[tid] = 0;
        red[tid] = ~0ull;
    }

    // ---- fused x row-norms: warp w handles rows w*8 .. w*8+7 ----
    #pragma unroll
    for (int i = 0; i < 8; i++) {
        int r = warp * 8 + i;
        float s = warp_rownorm(x + (size_t)(row0 + r) * DIM, lane);
        if (lane == 0) {
            x2s[r] = s;
            g_x2[row0 + r] = s;    // fb_kernel consumes this
        }
    }

    // ---- A prologue: 64 x rows -> bf16 fragment layout in smem ----
    {
        const int row = tid >> 2;
        const int p0 = (tid & 3) << 5;
        const int mb = row >> 4;
        const int lrow = (row & 7) << 2;
        const int hi = (row >> 3) & 1;
        const float2* xr2 = reinterpret_cast<const float2*>(
            x + (size_t)(row0 + row) * DIM);
        #pragma unroll 8
        for (int i = 0; i < 32; i++) {
            int p = p0 + i;              // d-pair index, d0 = 2p
            float2 v = xr2[p];
            uint32_t pk = bfpack(v.x, v.y);
            int d0 = p << 1;
            int kbg = d0 >> 4;
            int lfull = lrow | ((d0 & 7) >> 1);
            int reg = hi | (((d0 >> 3) & 1) << 1);
            As[((mb * 16 + kbg) << 7) + (lfull << 2) + reg] = pk;
        }
    }
    __syncthreads();

    float acc[2][8][4];

    for (int skt = 0; skt < 16; skt++) {
        #pragma unroll
        for (int rb = 0; rb < 2; rb++)
            #pragma unroll
            for (int nq = 0; nq < 8; nq++)
                #pragma unroll
                for (int cc = 0; cc < 4; cc++) acc[rb][nq][cc] = 0.f;

        for (int dc = 0; dc < 4; dc++) {
            int p = skt * 4 + dc;
            asm volatile("cp.async.wait_group 1;" ::: "memory");
            __syncthreads();
            const uint32_t* Bc = Bs + (p & 1) * 8192 + chalf * 4096;

            #pragma unroll
            for (int l = 0; l < 4; l++) {
                int kbg = dc * 4 + l;
                uint4 A4[2];
                #pragma unroll
                for (int rb = 0; rb < 2; rb++)
                    A4[rb] = *reinterpret_cast<const uint4*>(
                        As + (((wr * 2 + rb) * 16 + kbg) << 7) + (lane << 2));
                #pragma unroll
                for (int j = 0; j < 4; j++) {
                    uint4 Bp = *reinterpret_cast<const uint4*>(
                        Bc + (((l * 8 + qbase + j) * 32 + lane) << 2));
                    uint2 b0; b0.x = Bp.x; b0.y = Bp.y;
                    uint2 b1; b1.x = Bp.z; b1.y = Bp.w;
                    #pragma unroll
                    for (int rb = 0; rb < 2; rb++) {
                        MMA16(acc[rb][j * 2],     A4[rb], b0);
                        MMA16(acc[rb][j * 2 + 1], A4[rb], b1);
                    }
                }
            }
            __syncthreads();
            if (p + 2 < 64) LOAD_PAIR(p + 2);
        }

        // ---- epilogue pass 1: dist, shfl-reduced row-min ----
        const int cbase = skt * 256 + wn * 64;
        float e2v[8][2];
        #pragma unroll
        for (int nq = 0; nq < 8; nq++) {
            int c0 = cbase + nq * 8 + tig * 2;
            e2v[nq][0] = g_e2[c0];
            e2v[nq][1] = g_e2[c0 + 1];
        }
        #pragma unroll
        for (int rb = 0; rb < 2; rb++) {
            #pragma unroll
            for (int h = 0; h < 2; h++) {
                int r = wr * 32 + rb * 16 + gg + h * 8;
                float m = 3.4e38f;
                #pragma unroll
                for (int nq = 0; nq < 8; nq++)
                    #pragma unroll
                    for (int w = 0; w < 2; w++) {
                        int cc = h * 2 + w;
                        float dist = (x2s[r] + e2v[nq][w]) - 2.0f * acc[rb][nq][cc];
                        acc[rb][nq][cc] = dist;
                        m = fminf(m, dist);
                    }
                m = fminf(m, __shfl_xor_sync(0xffffffffu, m, 1));
                m = fminf(m, __shfl_xor_sync(0xffffffffu, m, 2));
                if (tig == 0) atomicMin(&rmin[r], fenc(m));
            }
        }
        __syncthreads();
        // ---- epilogue pass 2: collect with tight running-min threshold ----
        #pragma unroll
        for (int rb = 0; rb < 2; rb++)
            #pragma unroll
            for (int h = 0; h < 2; h++) {
                int r = wr * 32 + rb * 16 + gg + h * 8;
                float thr = fdec(rmin[r]) + TH;
                #pragma unroll
                for (int nq = 0; nq < 8; nq++)
                    #pragma unroll
                    for (int w = 0; w < 2; w++) {
                        if (acc[rb][nq][h * 2 + w] < thr) {
                            int s = atomicAdd(&scnt[r], 1);
                            if (s < CAND_MAX) {
                                int code = cbase + nq * 8 + tig * 2 + w;
                                cand[r * CAND_MAX + s] = (unsigned short)code;
                            }
                        }
                    }
            }
    }

    // ---- exact fp32 rescore ----
    __syncthreads();
    for (int t2 = 0; t2 < TROWS / 8; t2++) {
        int r = warp * (TROWS / 8) + t2;
        int c = scnt[r];
        if (c > CAND_MAX) {
            if (lane == 0) {
                int fi = atomicAdd(&g_fb_count, 1);
                g_fb_rows[fi] = row0 + r;
            }
            continue;
        }
        #pragma unroll
        for (int base = 0; base < CAND_MAX; base += 32) {
            int li = base + lane;
            if (li < c) {
                int idx = cand[r * CAND_MAX + li];
                float dist = exact_dist(x + (size_t)(row0 + r) * DIM,
                                        cb + (size_t)idx * DIM, x2s[r], g_e2[idx]);
                unsigned long long key =
                    ((unsigned long long)fenc(dist) << 32) | (unsigned)idx;
                atomicMin(&red[r], key);
            }
        }
    }
    __syncthreads();
    if (tid < TROWS && scnt[tid] <= CAND_MAX)
        g_idx[row0 + tid] = (int)(red[tid] & 0xFFFFFFFFu);
}

// ---------------------------------------------------------------------------
// Fallback: exact full scan for overflowed rows (parallel: 512 blocks).
// ---------------------------------------------------------------------------
__global__ void fb_kernel(const float* __restrict__ x, const float* __restrict__ cb) {
    __shared__ unsigned long long rr;
    int n = g_fb_count;
    for (int fi = blockIdx.x; fi < n; fi += gridDim.x) {
        int row = g_fb_rows[fi];
        if (threadIdx.x == 0) rr = ~0ull;
        __syncthreads();
        float x2 = g_x2[row];
        for (int c = threadIdx.x; c < KCB; c += blockDim.x) {
            float dist = exact_dist(x + (size_t)row * DIM, cb + (size_t)c * DIM,
                                    x2, g_e2[c]);
            unsigned long long key =
                ((unsigned long long)fenc(dist) << 32) | (unsigned)c;
            atomicMin(&rr, key);
        }
        __syncthreads();
        if (threadIdx.x == 0) g_idx[row] = (int)(rr & 0xFFFFFFFFu);
        __syncthreads();
    }
}

// ---------------------------------------------------------------------------
// Gather + straight-through output + loss partials.
// Warp per row, 4 rows unrolled: idx loaded once per row, 16 loads in flight.
// ---------------------------------------------------------------------------
__device__ __forceinline__ double st_elem(float4 xv, float4 q, float4& r) {
    float d0 = q.x - xv.x; r.x = xv.x + d0;
    float d1 = q.y - xv.y; r.y = xv.y + d1;
    float d2 = q.z - xv.z; r.z = xv.z + d2;
    float d3 = q.w - xv.w; r.w = xv.w + d3;
    return (double)(d0 * d0) + (double)(d1 * d1)
         + (double)(d2 * d2) + (double)(d3 * d3);
}

__global__ void vq_output_kernel(const float* __restrict__ x,
                                 const float* __restrict__ cb,
                                 float* __restrict__ out) {
    __shared__ double sred[256];
    const int lane = threadIdx.x & 31;
    const int gw = (blockIdx.x * blockDim.x + threadIdx.x) >> 5;
    const int nw = (gridDim.x * blockDim.x) >> 5;
    double lsum = 0.0;

    for (int row = gw * 4; row < NVEC; row += nw * 4) {
        int idx[4];
        #pragma unroll
        for (int k = 0; k < 4; k++) idx[k] = g_idx[row + k];

        float4 xa[4], xb[4], qa[4], qb[4];
        #pragma unroll
        for (int k = 0; k < 4; k++) {
            const float4* xr = reinterpret_cast<const float4*>(
                x + (size_t)(row + k) * DIM);
            const float4* cr = reinterpret_cast<const float4*>(
                cb + (size_t)idx[k] * DIM);
            xa[k] = xr[lane];
            xb[k] = xr[lane + 32];
            qa[k] = cr[lane];
            qb[k] = cr[lane + 32];
        }
        #pragma unroll
        for (int k = 0; k < 4; k++) {
            float4* o = reinterpret_cast<float4*>(out) + (size_t)(row + k) * 64;
            float4 r;
            lsum += st_elem(xa[k], qa[k], r); o[lane] = r;
            lsum += st_elem(xb[k], qb[k], r); o[lane + 32] = r;
        }
    }
    sred[threadIdx.x] = lsum;
    __syncthreads();
    #pragma unroll
    for (int s = 128; s; s >>= 1) {
        if (threadIdx.x < s) sred[threadIdx.x] += sred[threadIdx.x + s];
        __syncthreads();
    }
    if (threadIdx.x == 0) g_part[blockIdx.x] = sred[0];
}

__global__ void loss_kernel(float* __restrict__ out, int out_size) {
    __shared__ double sred[256];
    double s = 0.0;
    for (int i = threadIdx.x; i < LOSS_BLOCKS; i += 256) s += g_part[i];
    sred[threadIdx.x] = s;
    __syncthreads();
    #pragma unroll
    for (int k = 128; k; k >>= 1) {
        if (threadIdx.x < k) sred[threadIdx.x] += sred[threadIdx.x + k];
        __syncthreads();
    }
    const int nq = NVEC * DIM;
    if (threadIdx.x == 0) {
        double m = sred[0] / (double)nq;
        float mf = (float)m;
        float loss = mf + 0.25f * mf;
        if (out_size == nq + 1)      out[nq] = loss;
        else if (out_size == 1)      out[0] = loss;
        else if (out_size > nq)      out[out_size - 1] = loss;
    }
    for (int i = nq + 1 + threadIdx.x; i < out_size - 1; i += 256) out[i] = 0.f;
}

// ---------------------------------------------------------------------------
extern "C" void kernel_launch(void* const* d_in, const int* in_sizes, int n_in,
                              void* d_out, int out_size) {
    const float* x  = (const float*)d_in[0];
    const float* cb = (const float*)d_in[1];
    if (n_in >= 2 && in_sizes[0] == KCB * DIM && in_sizes[1] == NVEC * DIM) {
        const float* t = x; x = cb; cb = t;
    }
    float* out = (float*)d_out;

    cudaFuncSetAttribute(vq_mma_kernel,
                         cudaFuncAttributeMaxDynamicSharedMemorySize, 98304);

    bperm_kernel<<<KCB * DIM / 2 / 256, 256>>>(cb);
    rownorm_e_kernel<<<KCB / 8, 256>>>(cb);
    vq_mma_kernel<<<NTILES, 256, 98304>>>(x, cb);
    fb_kernel<<<512, 256>>>(x, cb);
    vq_output_kernel<<<LOSS_BLOCKS, 256>>>(x, cb, out);
    loss_kernel<<<1, 256>>>(out, out_size);
}